// round 14
// baseline (speedup 1.0000x reference)
#include <cuda_runtime.h>

#define LEN     262144
#define NFFT    1024
#define STRIDE  256
#define HALF    512
#define CUT     513
#define NFRM    1029
#define NB      32
#define PLANE   16892064u    // 32*513*1029
#define TB      8            // frames per block
#define FROW    1156         // fbuf row stride in floats (== 4 banks mod 32)

// DP-accurate tables in global memory (small, L1/L2-hot)
__device__ float2 g_tw[CUT];      // W_1024^j, j=0..512 (untangle)
__device__ float2 g_win2[HALF];   // Hann pairs (2j, 2j+1)
__device__ float2 g_T1[8 * 64];   // [ka][l]  = W_512^{l*ka}
__device__ float2 g_T2[8 * 8];    // [kc][n0] = W_64^{n0*kc}

__global__ void init_tables() {
    int j = blockIdx.x * blockDim.x + threadIdx.x;
    if (j < CUT) {
        double s, c;
        sincospi(-(double)j / 512.0, &s, &c);
        float2 w = make_float2((float)c, (float)s);
        if (j == 512) w = make_float2(-1.0f, 0.0f);  // pin: Xi[512] exactly +0
        if (j == 0)   w = make_float2( 1.0f, 0.0f);
        if (j == 256) w = make_float2( 0.0f, -1.0f);
        g_tw[j] = w;
    }
    if (j < HALF) {
        double s0, c0, s1, c1;
        sincospi(2.0 * (double)(2*j)     / (double)NFFT, &s0, &c0);
        sincospi(2.0 * (double)(2*j + 1) / (double)NFFT, &s1, &c1);
        g_win2[j] = make_float2((float)(0.5 - 0.5*c0), (float)(0.5 - 0.5*c1));
    }
    if (j < 8 * 64) {
        int ka = j >> 6, l = j & 63;
        double s, c;
        sincospi(-(double)(l * ka) / 256.0, &s, &c);   // W_512^{l*ka}
        g_T1[j] = make_float2((float)c, (float)s);
    }
    if (j < 8 * 8) {
        int kc = j >> 3, n0 = j & 7;
        double s, c;
        sincospi(-(double)(n0 * kc) / 32.0, &s, &c);   // W_64^{n0*kc}
        g_T2[j] = make_float2((float)c, (float)s);
    }
}

__device__ __forceinline__ float2 cmul(float2 a, float2 b) {
    return make_float2(fmaf(a.x, b.x, -a.y*b.y), fmaf(a.x, b.y, a.y*b.x));
}
__device__ __forceinline__ float2 cadd(float2 a, float2 b) { return make_float2(a.x+b.x, a.y+b.y); }
__device__ __forceinline__ float2 csub(float2 a, float2 b) { return make_float2(a.x-b.x, a.y-b.y); }

// Fast atan2 (max abs err ~1e-7 rad). Edge cases match numpy.
__device__ __forceinline__ float fast_atan2f(float y, float x) {
    float ax = fabsf(x), ay = fabsf(y);
    float mx = fmaxf(ax, ay), mn = fminf(ax, ay);
    float t = (mx > 0.f) ? __fdividef(mn, mx) : 0.f;   // [0,1]
    float s = t * t;
    float p =           -0.0040540580f;
    p = fmaf(p, s,       0.0218612288f);
    p = fmaf(p, s,      -0.0559098861f);
    p = fmaf(p, s,       0.0964200441f);
    p = fmaf(p, s,      -0.1390853351f);
    p = fmaf(p, s,       0.1994653599f);
    p = fmaf(p, s,      -0.3332985605f);
    p = fmaf(p, s,       0.9999993329f);
    float r = p * t;
    if (ay > ax)  r = 1.57079632679489662f - r;
    if (x < 0.f)  r = 3.14159265358979324f - r;
    return copysignf(r, y);
}

__device__ __forceinline__ float fast_sqrtf(float a) {
    float r;
    asm("sqrt.approx.f32 %0, %1;" : "=f"(r) : "f"(a));
    return r;
}

// y[r] = sum_j a[j] * W8^{j*r}
__device__ __forceinline__ void dft8(const float2 a[8], float2 y[8]) {
    float2 e0 = cadd(a[0], a[4]), e1 = csub(a[0], a[4]);
    float2 f0 = cadd(a[2], a[6]), f1 = csub(a[2], a[6]);
    float2 g0 = cadd(a[1], a[5]), g1 = csub(a[1], a[5]);
    float2 h0 = cadd(a[3], a[7]), h1 = csub(a[3], a[7]);
    float2 E0 = cadd(e0, f0), E2 = csub(e0, f0);
    float2 E1 = make_float2(e1.x + f1.y, e1.y - f1.x);   // e1 - i*f1
    float2 E3 = make_float2(e1.x - f1.y, e1.y + f1.x);   // e1 + i*f1
    float2 O0 = cadd(g0, h0), O2 = csub(g0, h0);
    float2 O1 = make_float2(g1.x + h1.y, g1.y - h1.x);
    float2 O3 = make_float2(g1.x - h1.y, g1.y + h1.x);
    const float C = 0.70710678118654752440f;
    float2 t1 = make_float2(C*(O1.x + O1.y), C*(O1.y - O1.x));    // W8^1*O1
    float2 t2 = make_float2(O2.y, -O2.x);                          // -i*O2
    float2 t3 = make_float2(C*(O3.y - O3.x), -C*(O3.x + O3.y));   // W8^3*O3
    y[0] = cadd(E0, O0); y[4] = csub(E0, O0);
    y[1] = cadd(E1, t1); y[5] = csub(E1, t1);
    y[2] = cadd(E2, t2); y[6] = csub(E2, t2);
    y[3] = cadd(E3, t3); y[7] = csub(E3, t3);
}

// 512 threads = 8 frames x 64 lanes. Register radix-8^3 FFT, scalar
// conflict-free smem exchanges. Conjugate-paired untangle fused into the
// store phase; stores hit full 32B sectors (8 contiguous t).
__global__ __launch_bounds__(512) void stft_kernel(const float* __restrict__ x,
                                                   float* __restrict__ out) {
    __shared__ float2 tw[CUT];            // 4104 B
    __shared__ float  fbuf[TB][FROW];     // 8 x 4624 B (exchanges / Z planes, aliased)

    const int tid = threadIdx.x;
    const int f   = tid >> 6;        // frame within block (0..7)
    const int l   = tid & 63;        // lane within frame
    const int t0  = blockIdx.x * TB;
    const int b   = blockIdx.y;
    const int t   = t0 + f;

    for (int r = tid; r < CUT; r += 512) tw[r] = g_tw[r];

    float*  base = fbuf[f];
    float2* b2   = (float2*)base;

    // ---- Pass 1: load (global->regs, windowed, packed), radix-8 over n2 ----
    const float* xb = x + (size_t)b * LEN;
    const int start = t * STRIDE - NFFT;      // always even
    float2 a[8], y[8];
    #pragma unroll
    for (int j = 0; j < 8; j++) {
        int n  = l + 64 * j;                  // packed complex index
        int i0 = start + 2 * n;
        float2 v = make_float2(0.f, 0.f);
        if (i0 >= 0 && i0 < LEN) v = *(const float2*)(xb + i0);
        float2 w = g_win2[n];
        a[j] = make_float2(v.x * w.x, v.y * w.y);
    }
    dft8(a, y);
    #pragma unroll
    for (int ka = 1; ka < 8; ka++) y[ka] = cmul(y[ka], g_T1[ka * 64 + l]);
    {   // exchange 1 write: idx = 72*n1 + n0 + 8*ka  (conflict-free)
        int n0 = l & 7, n1 = l >> 3;
        #pragma unroll
        for (int ka = 0; ka < 8; ka++) b2[72 * n1 + n0 + 8 * ka] = y[ka];
    }
    __syncthreads();

    // ---- Pass 2: thread (n0, ka), radix-8 over n1 ----
    {
        int n0 = l & 7, ka = l >> 3;
        #pragma unroll
        for (int n1 = 0; n1 < 8; n1++) a[n1] = b2[72 * n1 + n0 + 8 * ka];
        dft8(a, y);
        #pragma unroll
        for (int kc = 1; kc < 8; kc++) y[kc] = cmul(y[kc], g_T2[kc * 8 + n0]);
        __syncthreads();   // reads complete before aliased overwrite
        #pragma unroll
        for (int kc = 0; kc < 8; kc++) b2[65 * n0 + kc + 8 * ka] = y[kc];
    }
    __syncthreads();

    // ---- Pass 3: thread (kc, ka), radix-8 over n0; Z[ka + 8kc + 64kd] ----
    {
        int kc = l & 7, ka = l >> 3;
        #pragma unroll
        for (int n0 = 0; n0 < 8; n0++) a[n0] = b2[65 * n0 + kc + 8 * ka];
        dft8(a, y);
        __syncthreads();   // reads complete before aliased Z write
        float* zre = base;
        float* zim = base + 576;
        #pragma unroll
        for (int kd = 0; kd < 8; kd++) {
            int k  = ka + 8 * kc + 64 * kd;
            int zi = k + 4 * (k >> 5);        // conflict-free scalar layout
            zre[zi] = y[kd].x;
            zim[zi] = y[kd].y;
        }
    }
    __syncthreads();

    // ---- Fused conjugate-paired untangle + mag/angle + store ----
    // Thread (k0 = tid>>3, ff = tid&7): k = k0+64r (r<4, k<256) and pair 512-k
    // from the same Z reads, each with SINGLE rounding from shared
    // intermediates. Special: at (k0==0, r==0) the pair bin is k=512 where
    // si+ux == 0 exactly; Yi must be +0 (not -0) so atan2 gives +pi like numpy.
    {
        float* __restrict__ mag_out = out;
        float* __restrict__ ang_out = out + PLANE;
        const int k0 = tid >> 3;        // 0..63
        const int ff = tid & 7;
        const float* zre = fbuf[ff];
        const float* zim = fbuf[ff] + 576;
        if (t0 + ff < NFRM) {
            unsigned o1 = (unsigned)(b * CUT + k0)        * NFRM + (unsigned)(t0 + ff);
            unsigned o2 = (unsigned)(b * CUT + (512 - k0))* NFRM + (unsigned)(t0 + ff);
            #pragma unroll
            for (int r = 0; r < 4; r++) {
                int k  = k0 + 64 * r;          // [0, 256)
                int i2 = (512 - k) & 511;
                int z1 = k  + 4 * (k  >> 5);
                int z2 = i2 + 4 * (i2 >> 5);
                float Ax = zre[z1], Ay = zim[z1];
                float Bx = zre[z2], By = -zim[z2];
                float2 w = tw[k];
                float sr = Ax + Bx, si = Ay + By;
                float dr = Ax - Bx, di = Ay - By;
                float uy = fmaf(w.x, di,  w.y * dr);   // Im(w*(A-B))
                float ux = fmaf(w.x, dr, -w.y * di);   // Re(w*(A-B))
                float Xr =  0.5f * (sr + uy);
                float Xi =  0.5f * (si - ux);
                float Yr =  0.5f * (sr - uy);          // X[512-k], single rounding
                float Yi = -0.5f * (si + ux);
                if (r == 0 && k0 == 0) Yi = 0.0f;      // k=512: si+ux==0 exactly; pin +0
                mag_out[o1] = fast_sqrtf(fmaf(Xr, Xr, Xi * Xi));
                ang_out[o1] = fast_atan2f(Xi, Xr);
                mag_out[o2] = fast_sqrtf(fmaf(Yr, Yr, Yi * Yi));
                ang_out[o2] = fast_atan2f(Yi, Yr);
                o1 += 64u * NFRM;
                o2 -= 64u * NFRM;
            }
            if (k0 == 0) {                     // self-paired bin k = 256
                float Ax = zre[288], Ay = zim[288];    // z(256) = 256 + 4*8
                unsigned o = (unsigned)(b * CUT + 256) * NFRM + (unsigned)(t0 + ff);
                mag_out[o] = fast_sqrtf(fmaf(Ax, Ax, Ay * Ay));
                ang_out[o] = fast_atan2f(-Ay, Ax);     // X[256] = conj(Z[256])
            }
        }
    }
}

extern "C" void kernel_launch(void* const* d_in, const int* in_sizes, int n_in,
                              void* d_out, int out_size) {
    const float* x = (const float*)d_in[0];   // (32, 1, 262144) fp32
    float* out = (float*)d_out;               // mag plane then angle plane
    init_tables<<<(NFFT + 127) / 128, 128>>>();
    dim3 grid((NFRM + TB - 1) / TB, NB);      // 129 x 32
    stft_kernel<<<grid, 512>>>(x, out);
}

// round 15
// speedup vs baseline: 1.0468x; 1.0468x over previous
#include <cuda_runtime.h>

#define LEN     262144
#define NFFT    1024
#define STRIDE  256
#define HALF    512
#define CUT     513
#define NFRM    1029
#define NB      32
#define PLANE   16892064u    // 32*513*1029
#define TB      8            // frames per block
#define FROW    1156         // fbuf row stride in floats (== 4 banks mod 32)

// Per-frame barrier: syncs only the 64 lanes (2 warps) of frame f.
#define FRAME_BAR(f) asm volatile("bar.sync %0, 64;" :: "r"((f) + 1) : "memory")

// DP-accurate tables in global memory (small, L1/L2-hot)
__device__ float2 g_tw[CUT];      // W_1024^j, j=0..512 (untangle)
__device__ float2 g_win2[HALF];   // Hann pairs (2j, 2j+1)
__device__ float2 g_T1[8 * 64];   // [ka][l]  = W_512^{l*ka}
__device__ float2 g_T2[8 * 8];    // [kc][n0] = W_64^{n0*kc}

__global__ void init_tables() {
    int j = blockIdx.x * blockDim.x + threadIdx.x;
    if (j < CUT) {
        double s, c;
        sincospi(-(double)j / 512.0, &s, &c);
        float2 w = make_float2((float)c, (float)s);
        if (j == 512) w = make_float2(-1.0f, 0.0f);  // pin: Xi[512] exactly +0
        if (j == 0)   w = make_float2( 1.0f, 0.0f);
        if (j == 256) w = make_float2( 0.0f, -1.0f);
        g_tw[j] = w;
    }
    if (j < HALF) {
        double s0, c0, s1, c1;
        sincospi(2.0 * (double)(2*j)     / (double)NFFT, &s0, &c0);
        sincospi(2.0 * (double)(2*j + 1) / (double)NFFT, &s1, &c1);
        g_win2[j] = make_float2((float)(0.5 - 0.5*c0), (float)(0.5 - 0.5*c1));
    }
    if (j < 8 * 64) {
        int ka = j >> 6, l = j & 63;
        double s, c;
        sincospi(-(double)(l * ka) / 256.0, &s, &c);   // W_512^{l*ka}
        g_T1[j] = make_float2((float)c, (float)s);
    }
    if (j < 8 * 8) {
        int kc = j >> 3, n0 = j & 7;
        double s, c;
        sincospi(-(double)(n0 * kc) / 32.0, &s, &c);   // W_64^{n0*kc}
        g_T2[j] = make_float2((float)c, (float)s);
    }
}

__device__ __forceinline__ float2 cmul(float2 a, float2 b) {
    return make_float2(fmaf(a.x, b.x, -a.y*b.y), fmaf(a.x, b.y, a.y*b.x));
}
__device__ __forceinline__ float2 cadd(float2 a, float2 b) { return make_float2(a.x+b.x, a.y+b.y); }
__device__ __forceinline__ float2 csub(float2 a, float2 b) { return make_float2(a.x-b.x, a.y-b.y); }

// Fast atan2 (max abs err ~1e-7 rad). Edge cases match numpy.
__device__ __forceinline__ float fast_atan2f(float y, float x) {
    float ax = fabsf(x), ay = fabsf(y);
    float mx = fmaxf(ax, ay), mn = fminf(ax, ay);
    float t = (mx > 0.f) ? __fdividef(mn, mx) : 0.f;   // [0,1]
    float s = t * t;
    float p =           -0.0040540580f;
    p = fmaf(p, s,       0.0218612288f);
    p = fmaf(p, s,      -0.0559098861f);
    p = fmaf(p, s,       0.0964200441f);
    p = fmaf(p, s,      -0.1390853351f);
    p = fmaf(p, s,       0.1994653599f);
    p = fmaf(p, s,      -0.3332985605f);
    p = fmaf(p, s,       0.9999993329f);
    float r = p * t;
    if (ay > ax)  r = 1.57079632679489662f - r;
    if (x < 0.f)  r = 3.14159265358979324f - r;
    return copysignf(r, y);
}

__device__ __forceinline__ float fast_sqrtf(float a) {
    float r;
    asm("sqrt.approx.f32 %0, %1;" : "=f"(r) : "f"(a));
    return r;
}

// y[r] = sum_j a[j] * W8^{j*r}
__device__ __forceinline__ void dft8(const float2 a[8], float2 y[8]) {
    float2 e0 = cadd(a[0], a[4]), e1 = csub(a[0], a[4]);
    float2 f0 = cadd(a[2], a[6]), f1 = csub(a[2], a[6]);
    float2 g0 = cadd(a[1], a[5]), g1 = csub(a[1], a[5]);
    float2 h0 = cadd(a[3], a[7]), h1 = csub(a[3], a[7]);
    float2 E0 = cadd(e0, f0), E2 = csub(e0, f0);
    float2 E1 = make_float2(e1.x + f1.y, e1.y - f1.x);   // e1 - i*f1
    float2 E3 = make_float2(e1.x - f1.y, e1.y + f1.x);   // e1 + i*f1
    float2 O0 = cadd(g0, h0), O2 = csub(g0, h0);
    float2 O1 = make_float2(g1.x + h1.y, g1.y - h1.x);
    float2 O3 = make_float2(g1.x - h1.y, g1.y + h1.x);
    const float C = 0.70710678118654752440f;
    float2 t1 = make_float2(C*(O1.x + O1.y), C*(O1.y - O1.x));    // W8^1*O1
    float2 t2 = make_float2(O2.y, -O2.x);                          // -i*O2
    float2 t3 = make_float2(C*(O3.y - O3.x), -C*(O3.x + O3.y));   // W8^3*O3
    y[0] = cadd(E0, O0); y[4] = csub(E0, O0);
    y[1] = cadd(E1, t1); y[5] = csub(E1, t1);
    y[2] = cadd(E2, t2); y[6] = csub(E2, t2);
    y[3] = cadd(E3, t3); y[7] = csub(E3, t3);
}

// 512 threads = 8 frames x 64 lanes. Register radix-8^3 FFT, scalar
// conflict-free smem exchanges synced with PER-FRAME named barriers
// (2 warps each) -- the FFT has no cross-frame dependencies. One full
// __syncthreads before the cross-frame fused epilogue.
__global__ __launch_bounds__(512) void stft_kernel(const float* __restrict__ x,
                                                   float* __restrict__ out) {
    __shared__ float2 tw[CUT];            // 4104 B
    __shared__ float  fbuf[TB][FROW];     // 8 x 4624 B (exchanges / Z planes, aliased)

    const int tid = threadIdx.x;
    const int f   = tid >> 6;        // frame within block (0..7)
    const int l   = tid & 63;        // lane within frame
    const int t0  = blockIdx.x * TB;
    const int b   = blockIdx.y;
    const int t   = t0 + f;

    for (int r = tid; r < CUT; r += 512) tw[r] = g_tw[r];  // consumed after full sync

    float*  base = fbuf[f];
    float2* b2   = (float2*)base;

    // ---- Pass 1: load (global->regs, windowed, packed), radix-8 over n2 ----
    const float* xb = x + (size_t)b * LEN;
    const int start = t * STRIDE - NFFT;      // always even
    float2 a[8], y[8];
    #pragma unroll
    for (int j = 0; j < 8; j++) {
        int n  = l + 64 * j;                  // packed complex index
        int i0 = start + 2 * n;
        float2 v = make_float2(0.f, 0.f);
        if (i0 >= 0 && i0 < LEN) v = *(const float2*)(xb + i0);
        float2 w = g_win2[n];
        a[j] = make_float2(v.x * w.x, v.y * w.y);
    }
    dft8(a, y);
    #pragma unroll
    for (int ka = 1; ka < 8; ka++) y[ka] = cmul(y[ka], g_T1[ka * 64 + l]);
    {   // exchange 1 write: idx = 72*n1 + n0 + 8*ka  (conflict-free)
        int n0 = l & 7, n1 = l >> 3;
        #pragma unroll
        for (int ka = 0; ka < 8; ka++) b2[72 * n1 + n0 + 8 * ka] = y[ka];
    }
    FRAME_BAR(f);

    // ---- Pass 2: thread (n0, ka), radix-8 over n1 ----
    {
        int n0 = l & 7, ka = l >> 3;
        #pragma unroll
        for (int n1 = 0; n1 < 8; n1++) a[n1] = b2[72 * n1 + n0 + 8 * ka];
        dft8(a, y);
        #pragma unroll
        for (int kc = 1; kc < 8; kc++) y[kc] = cmul(y[kc], g_T2[kc * 8 + n0]);
        FRAME_BAR(f);      // frame's reads complete before aliased overwrite
        #pragma unroll
        for (int kc = 0; kc < 8; kc++) b2[65 * n0 + kc + 8 * ka] = y[kc];
    }
    FRAME_BAR(f);

    // ---- Pass 3: thread (kc, ka), radix-8 over n0; Z[ka + 8kc + 64kd] ----
    {
        int kc = l & 7, ka = l >> 3;
        #pragma unroll
        for (int n0 = 0; n0 < 8; n0++) a[n0] = b2[65 * n0 + kc + 8 * ka];
        dft8(a, y);
        FRAME_BAR(f);      // frame's reads complete before aliased Z write
        float* zre = base;
        float* zim = base + 576;
        #pragma unroll
        for (int kd = 0; kd < 8; kd++) {
            int k  = ka + 8 * kc + 64 * kd;
            int zi = k + 4 * (k >> 5);        // conflict-free scalar layout
            zre[zi] = y[kd].x;
            zim[zi] = y[kd].y;
        }
    }
    __syncthreads();       // cross-frame: all Z planes ready, tw ready

    // ---- Fused conjugate-paired untangle + mag/angle + store ----
    // Thread (k0 = tid>>3, ff = tid&7): k = k0+64r (r<4, k<256) and pair 512-k
    // from the same Z reads, each with SINGLE rounding from shared
    // intermediates. Special: at (k0==0, r==0) the pair bin is k=512 where
    // si+ux == 0 exactly; Yi must be +0 (not -0) so atan2 gives +pi like numpy.
    {
        float* __restrict__ mag_out = out;
        float* __restrict__ ang_out = out + PLANE;
        const int k0 = tid >> 3;        // 0..63
        const int ff = tid & 7;
        const float* zre = fbuf[ff];
        const float* zim = fbuf[ff] + 576;
        if (t0 + ff < NFRM) {
            unsigned o1 = (unsigned)(b * CUT + k0)        * NFRM + (unsigned)(t0 + ff);
            unsigned o2 = (unsigned)(b * CUT + (512 - k0))* NFRM + (unsigned)(t0 + ff);
            #pragma unroll
            for (int r = 0; r < 4; r++) {
                int k  = k0 + 64 * r;          // [0, 256)
                int i2 = (512 - k) & 511;
                int z1 = k  + 4 * (k  >> 5);
                int z2 = i2 + 4 * (i2 >> 5);
                float Ax = zre[z1], Ay = zim[z1];
                float Bx = zre[z2], By = -zim[z2];
                float2 w = tw[k];
                float sr = Ax + Bx, si = Ay + By;
                float dr = Ax - Bx, di = Ay - By;
                float uy = fmaf(w.x, di,  w.y * dr);   // Im(w*(A-B))
                float ux = fmaf(w.x, dr, -w.y * di);   // Re(w*(A-B))
                float Xr =  0.5f * (sr + uy);
                float Xi =  0.5f * (si - ux);
                float Yr =  0.5f * (sr - uy);          // X[512-k], single rounding
                float Yi = -0.5f * (si + ux);
                if (r == 0 && k0 == 0) Yi = 0.0f;      // k=512: si+ux==0 exactly; pin +0
                mag_out[o1] = fast_sqrtf(fmaf(Xr, Xr, Xi * Xi));
                ang_out[o1] = fast_atan2f(Xi, Xr);
                mag_out[o2] = fast_sqrtf(fmaf(Yr, Yr, Yi * Yi));
                ang_out[o2] = fast_atan2f(Yi, Yr);
                o1 += 64u * NFRM;
                o2 -= 64u * NFRM;
            }
            if (k0 == 0) {                     // self-paired bin k = 256
                float Ax = zre[288], Ay = zim[288];    // z(256) = 256 + 4*8
                unsigned o = (unsigned)(b * CUT + 256) * NFRM + (unsigned)(t0 + ff);
                mag_out[o] = fast_sqrtf(fmaf(Ax, Ax, Ay * Ay));
                ang_out[o] = fast_atan2f(-Ay, Ax);     // X[256] = conj(Z[256])
            }
        }
    }
}

extern "C" void kernel_launch(void* const* d_in, const int* in_sizes, int n_in,
                              void* d_out, int out_size) {
    const float* x = (const float*)d_in[0];   // (32, 1, 262144) fp32
    float* out = (float*)d_out;               // mag plane then angle plane
    init_tables<<<(NFFT + 127) / 128, 128>>>();
    dim3 grid((NFRM + TB - 1) / TB, NB);      // 129 x 32
    stft_kernel<<<grid, 512>>>(x, out);
}

// round 16
// speedup vs baseline: 1.0506x; 1.0036x over previous
#include <cuda_runtime.h>

#define LEN     262144
#define NFFT    1024
#define STRIDE  256
#define HALF    512
#define CUT     513
#define NFRM    1029
#define NB      32
#define PLANE   16892064u    // 32*513*1029
#define TB      8            // frames per block
#define FROW    1156         // fbuf row stride in floats (== 4 banks mod 32)

// Per-frame barrier: syncs only the 64 lanes (2 warps) of frame f.
#define FRAME_BAR(f) asm volatile("bar.sync %0, 64;" :: "r"((f) + 1) : "memory")

typedef unsigned long long u64p;   // packed f32x2 (lo = .x, hi = .y)

// ---- packed f32x2 primitives (sm_100+; FFMA2/FADD2 path, PTX-only) ----
__device__ __forceinline__ u64p p_add(u64p a, u64p b) {
    u64p r; asm("add.rn.f32x2 %0, %1, %2;" : "=l"(r) : "l"(a), "l"(b)); return r;
}
__device__ __forceinline__ u64p p_mul(u64p a, u64p b) {
    u64p r; asm("mul.rn.f32x2 %0, %1, %2;" : "=l"(r) : "l"(a), "l"(b)); return r;
}
__device__ __forceinline__ u64p p_fma(u64p a, u64p b, u64p c) {
    u64p r; asm("fma.rn.f32x2 %0, %1, %2, %3;" : "=l"(r) : "l"(a), "l"(b), "l"(c)); return r;
}
__device__ __forceinline__ u64p p_pk(float x, float y) {
    u64p r; asm("mov.b64 %0, {%1, %2};" : "=l"(r) : "f"(x), "f"(y)); return r;
}
__device__ __forceinline__ float2 p_up(u64p a) {
    float2 v; asm("mov.b64 {%0, %1}, %2;" : "=f"(v.x), "=f"(v.y) : "l"(a)); return v;
}
#define PNEG1  0xBF800000BF800000ULL   // (-1, -1)
#define PCC    0x3F3504F33F3504F3ULL   // (c, c), c = cos(pi/4)
#define PHALF  0x3F0000003F000000ULL   // (0.5, 0.5)
#define PHALFN 0xBF0000003F000000ULL   // (0.5, -0.5)
// exact subtract: a - b == fma(b, -1, a), identical rounding to scalar FADD
__device__ __forceinline__ u64p p_sub(u64p a, u64p b) { return p_fma(b, (u64p)PNEG1, a); }

// DP-accurate tables in global memory (small, L1/L2-hot)
__device__ float2 g_tw[CUT];      // W_1024^j, j=0..512 (untangle)
__device__ float2 g_win2[HALF];   // Hann pairs (2j, 2j+1)
__device__ float2 g_T1[8 * 64];   // [ka][l]  = W_512^{l*ka}
__device__ float2 g_T2[8 * 8];    // [kc][n0] = W_64^{n0*kc}

__global__ void init_tables() {
    int j = blockIdx.x * blockDim.x + threadIdx.x;
    if (j < CUT) {
        double s, c;
        sincospi(-(double)j / 512.0, &s, &c);
        float2 w = make_float2((float)c, (float)s);
        if (j == 512) w = make_float2(-1.0f, 0.0f);  // pin: Xi[512] exactly +0
        if (j == 0)   w = make_float2( 1.0f, 0.0f);
        if (j == 256) w = make_float2( 0.0f, -1.0f);
        g_tw[j] = w;
    }
    if (j < HALF) {
        double s0, c0, s1, c1;
        sincospi(2.0 * (double)(2*j)     / (double)NFFT, &s0, &c0);
        sincospi(2.0 * (double)(2*j + 1) / (double)NFFT, &s1, &c1);
        g_win2[j] = make_float2((float)(0.5 - 0.5*c0), (float)(0.5 - 0.5*c1));
    }
    if (j < 8 * 64) {
        int ka = j >> 6, l = j & 63;
        double s, c;
        sincospi(-(double)(l * ka) / 256.0, &s, &c);   // W_512^{l*ka}
        g_T1[j] = make_float2((float)c, (float)s);
    }
    if (j < 8 * 8) {
        int kc = j >> 3, n0 = j & 7;
        double s, c;
        sincospi(-(double)(n0 * kc) / 32.0, &s, &c);   // W_64^{n0*kc}
        g_T2[j] = make_float2((float)c, (float)s);
    }
}

__device__ __forceinline__ float2 cmul(float2 a, float2 b) {
    return make_float2(fmaf(a.x, b.x, -a.y*b.y), fmaf(a.x, b.y, a.y*b.x));
}

// Fast atan2 (max abs err ~1e-7 rad). Edge cases match numpy.
__device__ __forceinline__ float fast_atan2f(float y, float x) {
    float ax = fabsf(x), ay = fabsf(y);
    float mx = fmaxf(ax, ay), mn = fminf(ax, ay);
    float t = (mx > 0.f) ? __fdividef(mn, mx) : 0.f;   // [0,1]
    float s = t * t;
    float p =           -0.0040540580f;
    p = fmaf(p, s,       0.0218612288f);
    p = fmaf(p, s,      -0.0559098861f);
    p = fmaf(p, s,       0.0964200441f);
    p = fmaf(p, s,      -0.1390853351f);
    p = fmaf(p, s,       0.1994653599f);
    p = fmaf(p, s,      -0.3332985605f);
    p = fmaf(p, s,       0.9999993329f);
    float r = p * t;
    if (ay > ax)  r = 1.57079632679489662f - r;
    if (x < 0.f)  r = 3.14159265358979324f - r;
    return copysignf(r, y);
}

__device__ __forceinline__ float fast_sqrtf(float a) {
    float r;
    asm("sqrt.approx.f32 %0, %1;" : "=f"(r) : "f"(a));
    return r;
}

// Packed radix-8 DFT: y[r] = sum_j a[j] * W8^{j*r}. Lane-for-lane identical
// rounding to the scalar version (p_sub is a fused exact -1 multiply).
__device__ __forceinline__ void dft8_p(const u64p a[8], u64p y[8]) {
    u64p e0 = p_add(a[0], a[4]), e1 = p_sub(a[0], a[4]);
    u64p f0 = p_add(a[2], a[6]), f1 = p_sub(a[2], a[6]);
    u64p g0 = p_add(a[1], a[5]), g1 = p_sub(a[1], a[5]);
    u64p h0 = p_add(a[3], a[7]), h1 = p_sub(a[3], a[7]);
    u64p E0 = p_add(e0, f0), E2 = p_sub(e0, f0);
    float2 f1u = p_up(f1); u64p fj = p_pk(f1u.y, -f1u.x);   // -i*f1
    u64p E1 = p_add(e1, fj), E3 = p_sub(e1, fj);
    u64p O0 = p_add(g0, h0), O2 = p_sub(g0, h0);
    float2 h1u = p_up(h1); u64p hj = p_pk(h1u.y, -h1u.x);   // -i*h1
    u64p O1 = p_add(g1, hj), O3 = p_sub(g1, hj);
    float2 O1u = p_up(O1);
    u64p t1 = p_mul(p_pk(O1u.x + O1u.y, O1u.y - O1u.x), (u64p)PCC);   // W8^1*O1
    float2 O2u = p_up(O2);
    u64p t2 = p_pk(O2u.y, -O2u.x);                                    // -i*O2
    float2 O3u = p_up(O3);
    u64p t3 = p_mul(p_pk(O3u.y - O3u.x, -(O3u.x + O3u.y)), (u64p)PCC);// W8^3*O3
    y[0] = p_add(E0, O0); y[4] = p_sub(E0, O0);
    y[1] = p_add(E1, t1); y[5] = p_sub(E1, t1);
    y[2] = p_add(E2, t2); y[6] = p_sub(E2, t2);
    y[3] = p_add(E3, t3); y[7] = p_sub(E3, t3);
}

// 512 threads = 8 frames x 64 lanes. Packed-f32x2 register radix-8^3 FFT,
// scalar conflict-free smem exchanges, per-frame named barriers, fused
// conjugate-paired epilogue with full-sector stores.
__global__ __launch_bounds__(512) void stft_kernel(const float* __restrict__ x,
                                                   float* __restrict__ out) {
    __shared__ float2 tw[CUT];            // 4104 B
    __shared__ float  fbuf[TB][FROW];     // 8 x 4624 B (exchanges / Z planes, aliased)

    const int tid = threadIdx.x;
    const int f   = tid >> 6;        // frame within block (0..7)
    const int l   = tid & 63;        // lane within frame
    const int t0  = blockIdx.x * TB;
    const int b   = blockIdx.y;
    const int t   = t0 + f;

    for (int r = tid; r < CUT; r += 512) tw[r] = g_tw[r];  // consumed after full sync

    float* base = fbuf[f];
    u64p*  b8   = (u64p*)base;       // 8B-aligned (frame offset 4624B = 578*8)

    // ---- Pass 1: load (global->regs, windowed, packed), radix-8 over n2 ----
    const float* xb = x + (size_t)b * LEN;
    const int start = t * STRIDE - NFFT;      // always even
    u64p a[8], y[8];
    const u64p* win8 = (const u64p*)g_win2;
    #pragma unroll
    for (int j = 0; j < 8; j++) {
        int n  = l + 64 * j;                  // packed complex index
        int i0 = start + 2 * n;
        u64p v = 0ULL;
        if (i0 >= 0 && i0 < LEN) v = *(const u64p*)(xb + i0);  // 8B-aligned (i0 even)
        a[j] = p_mul(v, win8[n]);             // (x_e*w_e, x_o*w_o)
    }
    dft8_p(a, y);
    #pragma unroll
    for (int ka = 1; ka < 8; ka++) {          // scalar cmul (packing costs movs)
        float2 yu = p_up(y[ka]);
        float2 r  = cmul(yu, g_T1[ka * 64 + l]);
        y[ka] = p_pk(r.x, r.y);
    }
    {   // exchange 1 write: idx = 72*n1 + n0 + 8*ka  (conflict-free)
        int n0 = l & 7, n1 = l >> 3;
        #pragma unroll
        for (int ka = 0; ka < 8; ka++) b8[72 * n1 + n0 + 8 * ka] = y[ka];
    }
    FRAME_BAR(f);

    // ---- Pass 2: thread (n0, ka), radix-8 over n1 ----
    {
        int n0 = l & 7, ka = l >> 3;
        #pragma unroll
        for (int n1 = 0; n1 < 8; n1++) a[n1] = b8[72 * n1 + n0 + 8 * ka];
        dft8_p(a, y);
        #pragma unroll
        for (int kc = 1; kc < 8; kc++) {
            float2 yu = p_up(y[kc]);
            float2 r  = cmul(yu, g_T2[kc * 8 + n0]);
            y[kc] = p_pk(r.x, r.y);
        }
        FRAME_BAR(f);      // frame's reads complete before aliased overwrite
        #pragma unroll
        for (int kc = 0; kc < 8; kc++) b8[65 * n0 + kc + 8 * ka] = y[kc];
    }
    FRAME_BAR(f);

    // ---- Pass 3: thread (kc, ka), radix-8 over n0; Z[ka + 8kc + 64kd] ----
    {
        int kc = l & 7, ka = l >> 3;
        #pragma unroll
        for (int n0 = 0; n0 < 8; n0++) a[n0] = b8[65 * n0 + kc + 8 * ka];
        dft8_p(a, y);
        FRAME_BAR(f);      // frame's reads complete before aliased Z write
        float* zre = base;
        float* zim = base + 576;
        #pragma unroll
        for (int kd = 0; kd < 8; kd++) {
            int k  = ka + 8 * kc + 64 * kd;
            int zi = k + 4 * (k >> 5);        // conflict-free scalar layout
            float2 yu = p_up(y[kd]);
            zre[zi] = yu.x;
            zim[zi] = yu.y;
        }
    }
    __syncthreads();       // cross-frame: all Z planes ready, tw ready

    // ---- Fused conjugate-paired untangle + mag/angle + store ----
    // Thread (k0 = tid>>3, ff = tid&7): k = k0+64r (r<4) and pair 512-k from
    // the same Z reads, packed lane math with single rounding per component.
    // Special: at (k0==0, r==0) the pair bin is k=512 where si+ux == 0
    // exactly; Yi must be +0 (not -0) so atan2 gives +pi like numpy.
    {
        float* __restrict__ mag_out = out;
        float* __restrict__ ang_out = out + PLANE;
        const int k0 = tid >> 3;        // 0..63
        const int ff = tid & 7;
        const float* zre = fbuf[ff];
        const float* zim = fbuf[ff] + 576;
        if (t0 + ff < NFRM) {
            unsigned o1 = (unsigned)(b * CUT + k0)        * NFRM + (unsigned)(t0 + ff);
            unsigned o2 = (unsigned)(b * CUT + (512 - k0))* NFRM + (unsigned)(t0 + ff);
            #pragma unroll
            for (int r = 0; r < 4; r++) {
                int k  = k0 + 64 * r;          // [0, 256)
                int i2 = (512 - k) & 511;
                int z1 = k  + 4 * (k  >> 5);
                int z2 = i2 + 4 * (i2 >> 5);
                u64p A  = p_pk(zre[z1], zim[z1]);
                u64p Bc = p_pk(zre[z2], -zim[z2]);         // conj
                u64p S  = p_add(A, Bc);                    // (sr, si)
                u64p Dd = p_sub(A, Bc);                    // (dr, di)
                float2 d2 = p_up(Dd);
                float2 w  = tw[k];
                float uy = fmaf(w.x, d2.y,  w.y * d2.x);   // Im(w*(A-B))
                float ux = fmaf(w.x, d2.x, -w.y * d2.y);   // Re(w*(A-B))
                u64p U2 = p_pk(uy, ux);
                float2 V  = p_up(p_add(S, U2));            // (sr+uy, si+ux)
                float2 Dv = p_up(p_sub(S, U2));            // (sr-uy, si-ux)
                float2 X = p_up(p_mul(p_pk(V.x, Dv.y), (u64p)PHALF));   // (Xr, Xi)
                float2 Y = p_up(p_mul(p_pk(Dv.x, V.y), (u64p)PHALFN));  // (Yr, -0.5(si+ux))
                if (r == 0 && k0 == 0) Y.y = 0.0f;         // k=512: pin Yi = +0
                mag_out[o1] = fast_sqrtf(fmaf(X.x, X.x, X.y * X.y));
                ang_out[o1] = fast_atan2f(X.y, X.x);
                mag_out[o2] = fast_sqrtf(fmaf(Y.x, Y.x, Y.y * Y.y));
                ang_out[o2] = fast_atan2f(Y.y, Y.x);
                o1 += 64u * NFRM;
                o2 -= 64u * NFRM;
            }
            if (k0 == 0) {                     // self-paired bin k = 256
                float Ax = zre[288], Ay = zim[288];    // z(256) = 256 + 4*8
                unsigned o = (unsigned)(b * CUT + 256) * NFRM + (unsigned)(t0 + ff);
                mag_out[o] = fast_sqrtf(fmaf(Ax, Ax, Ay * Ay));
                ang_out[o] = fast_atan2f(-Ay, Ax);     // X[256] = conj(Z[256])
            }
        }
    }
}

extern "C" void kernel_launch(void* const* d_in, const int* in_sizes, int n_in,
                              void* d_out, int out_size) {
    const float* x = (const float*)d_in[0];   // (32, 1, 262144) fp32
    float* out = (float*)d_out;               // mag plane then angle plane
    init_tables<<<(NFFT + 127) / 128, 128>>>();
    dim3 grid((NFRM + TB - 1) / TB, NB);      // 129 x 32
    stft_kernel<<<grid, 512>>>(x, out);
}

// round 17
// speedup vs baseline: 1.0847x; 1.0325x over previous
#include <cuda_runtime.h>

#define LEN     262144
#define NFFT    1024
#define STRIDE  256
#define HALF    512
#define CUT     513
#define NFRM    1029
#define NB      32
#define PLANE   16892064u    // 32*513*1029
#define TB      8            // frames per block
#define FROW    1156         // fbuf row stride in floats (== 4 banks mod 32)

// Per-frame barrier: syncs only the 64 lanes (2 warps) of frame f.
#define FRAME_BAR(f) asm volatile("bar.sync %0, 64;" :: "r"((f) + 1) : "memory")

typedef unsigned long long u64p;   // packed f32x2 (lo = .x, hi = .y)

// ---- packed f32x2 primitives (sm_100+; FFMA2/FADD2 path, PTX-only) ----
__device__ __forceinline__ u64p p_add(u64p a, u64p b) {
    u64p r; asm("add.rn.f32x2 %0, %1, %2;" : "=l"(r) : "l"(a), "l"(b)); return r;
}
__device__ __forceinline__ u64p p_mul(u64p a, u64p b) {
    u64p r; asm("mul.rn.f32x2 %0, %1, %2;" : "=l"(r) : "l"(a), "l"(b)); return r;
}
__device__ __forceinline__ u64p p_fma(u64p a, u64p b, u64p c) {
    u64p r; asm("fma.rn.f32x2 %0, %1, %2, %3;" : "=l"(r) : "l"(a), "l"(b), "l"(c)); return r;
}
__device__ __forceinline__ u64p p_pk(float x, float y) {
    u64p r; asm("mov.b64 %0, {%1, %2};" : "=l"(r) : "f"(x), "f"(y)); return r;
}
__device__ __forceinline__ float2 p_up(u64p a) {
    float2 v; asm("mov.b64 {%0, %1}, %2;" : "=f"(v.x), "=f"(v.y) : "l"(a)); return v;
}
#define PNEG1  0xBF800000BF800000ULL   // (-1, -1)
#define PCC    0x3F3504F33F3504F3ULL   // (c, c), c = cos(pi/4)
#define PHALF  0x3F0000003F000000ULL   // (0.5, 0.5)
#define PHALFN 0xBF0000003F000000ULL   // (0.5, -0.5)
// exact subtract: a - b == fma(b, -1, a), identical rounding to scalar FADD
__device__ __forceinline__ u64p p_sub(u64p a, u64p b) { return p_fma(b, (u64p)PNEG1, a); }

// DP-accurate tables in global memory (small, L1/L2-hot)
__device__ float2 g_tw[CUT];      // W_1024^j, j=0..512 (untangle)
__device__ float2 g_win2[HALF];   // Hann pairs (2j, 2j+1)
__device__ float2 g_T1[8 * 64];   // [ka][l]  = W_512^{l*ka}
__device__ float2 g_T2[8 * 8];    // [kc][n0] = W_64^{n0*kc}

// One table entry per thread (single DP sincospi on the critical path).
// Entry layout: [0,513) tw | [513,1025) win pairs* | [1025,1537) T1 | [1537,1601) T2
// *win entries computed as two sincospi? No: win pair (2j,2j+1) -> handled as
//  TWO entries (one per sample) writing halves of g_win2.
//   [513, 1537): win sample n = e-513 (1024 samples, one half each)
//   [1537, 2049): T1
//   [2049, 2113): T2
__global__ void init_tables() {
    int e = blockIdx.x * blockDim.x + threadIdx.x;
    if (e < 513) {
        int j = e;
        double s, c;
        sincospi(-(double)j / 512.0, &s, &c);
        float2 w = make_float2((float)c, (float)s);
        if (j == 512) w = make_float2(-1.0f, 0.0f);  // pin: Xi[512] exactly +0
        if (j == 0)   w = make_float2( 1.0f, 0.0f);
        if (j == 256) w = make_float2( 0.0f, -1.0f);
        g_tw[j] = w;
    } else if (e < 513 + NFFT) {
        int n = e - 513;                       // 0..1023, one window sample
        double s, c;
        sincospi(2.0 * (double)n / (double)NFFT, &s, &c);
        float v = (float)(0.5 - 0.5 * c);
        ((float*)g_win2)[n] = v;               // g_win2[n>>1].{x if even, y if odd}
    } else if (e < 513 + NFFT + 512) {
        int j = e - (513 + NFFT);              // 0..511
        int ka = j >> 6, l = j & 63;
        double s, c;
        sincospi(-(double)(l * ka) / 256.0, &s, &c);   // W_512^{l*ka}
        g_T1[j] = make_float2((float)c, (float)s);
    } else if (e < 513 + NFFT + 512 + 64) {
        int j = e - (513 + NFFT + 512);        // 0..63
        int kc = j >> 3, n0 = j & 7;
        double s, c;
        sincospi(-(double)(n0 * kc) / 32.0, &s, &c);   // W_64^{n0*kc}
        g_T2[j] = make_float2((float)c, (float)s);
    }
}
#define INIT_ENTRIES (513 + NFFT + 512 + 64)   // 2113

__device__ __forceinline__ float2 cmul(float2 a, float2 b) {
    return make_float2(fmaf(a.x, b.x, -a.y*b.y), fmaf(a.x, b.y, a.y*b.x));
}

// Fast atan2 (max abs err ~1e-7 rad). Edge cases match numpy.
__device__ __forceinline__ float fast_atan2f(float y, float x) {
    float ax = fabsf(x), ay = fabsf(y);
    float mx = fmaxf(ax, ay), mn = fminf(ax, ay);
    float t = (mx > 0.f) ? __fdividef(mn, mx) : 0.f;   // [0,1]
    float s = t * t;
    float p =           -0.0040540580f;
    p = fmaf(p, s,       0.0218612288f);
    p = fmaf(p, s,      -0.0559098861f);
    p = fmaf(p, s,       0.0964200441f);
    p = fmaf(p, s,      -0.1390853351f);
    p = fmaf(p, s,       0.1994653599f);
    p = fmaf(p, s,      -0.3332985605f);
    p = fmaf(p, s,       0.9999993329f);
    float r = p * t;
    if (ay > ax)  r = 1.57079632679489662f - r;
    if (x < 0.f)  r = 3.14159265358979324f - r;
    return copysignf(r, y);
}

__device__ __forceinline__ float fast_sqrtf(float a) {
    float r;
    asm("sqrt.approx.f32 %0, %1;" : "=f"(r) : "f"(a));
    return r;
}

// Packed radix-8 DFT: y[r] = sum_j a[j] * W8^{j*r}. Lane-for-lane identical
// rounding to the scalar version (p_sub is a fused exact -1 multiply).
__device__ __forceinline__ void dft8_p(const u64p a[8], u64p y[8]) {
    u64p e0 = p_add(a[0], a[4]), e1 = p_sub(a[0], a[4]);
    u64p f0 = p_add(a[2], a[6]), f1 = p_sub(a[2], a[6]);
    u64p g0 = p_add(a[1], a[5]), g1 = p_sub(a[1], a[5]);
    u64p h0 = p_add(a[3], a[7]), h1 = p_sub(a[3], a[7]);
    u64p E0 = p_add(e0, f0), E2 = p_sub(e0, f0);
    float2 f1u = p_up(f1); u64p fj = p_pk(f1u.y, -f1u.x);   // -i*f1
    u64p E1 = p_add(e1, fj), E3 = p_sub(e1, fj);
    u64p O0 = p_add(g0, h0), O2 = p_sub(g0, h0);
    float2 h1u = p_up(h1); u64p hj = p_pk(h1u.y, -h1u.x);   // -i*h1
    u64p O1 = p_add(g1, hj), O3 = p_sub(g1, hj);
    float2 O1u = p_up(O1);
    u64p t1 = p_mul(p_pk(O1u.x + O1u.y, O1u.y - O1u.x), (u64p)PCC);   // W8^1*O1
    float2 O2u = p_up(O2);
    u64p t2 = p_pk(O2u.y, -O2u.x);                                    // -i*O2
    float2 O3u = p_up(O3);
    u64p t3 = p_mul(p_pk(O3u.y - O3u.x, -(O3u.x + O3u.y)), (u64p)PCC);// W8^3*O3
    y[0] = p_add(E0, O0); y[4] = p_sub(E0, O0);
    y[1] = p_add(E1, t1); y[5] = p_sub(E1, t1);
    y[2] = p_add(E2, t2); y[6] = p_sub(E2, t2);
    y[3] = p_add(E3, t3); y[7] = p_sub(E3, t3);
}

// 512 threads = 8 frames x 64 lanes. Packed-f32x2 register radix-8^3 FFT,
// scalar conflict-free smem exchanges, per-frame named barriers, fused
// conjugate-paired epilogue with full-sector stores.
__global__ __launch_bounds__(512) void stft_kernel(const float* __restrict__ x,
                                                   float* __restrict__ out) {
    __shared__ float2 tw[CUT];            // 4104 B
    __shared__ float  fbuf[TB][FROW];     // 8 x 4624 B (exchanges / Z planes, aliased)

    const int tid = threadIdx.x;
    const int f   = tid >> 6;        // frame within block (0..7)
    const int l   = tid & 63;        // lane within frame
    const int t0  = blockIdx.x * TB;
    const int b   = blockIdx.y;
    const int t   = t0 + f;

    for (int r = tid; r < CUT; r += 512) tw[r] = g_tw[r];  // consumed after full sync

    float* base = fbuf[f];
    u64p*  b8   = (u64p*)base;       // 8B-aligned (frame offset 4624B = 578*8)

    // ---- Pass 1: load (global->regs, windowed, packed), radix-8 over n2 ----
    const float* xb = x + (size_t)b * LEN;
    const int start = t * STRIDE - NFFT;      // always even
    u64p a[8], y[8];
    const u64p* win8 = (const u64p*)g_win2;
    #pragma unroll
    for (int j = 0; j < 8; j++) {
        int n  = l + 64 * j;                  // packed complex index
        int i0 = start + 2 * n;
        u64p v = 0ULL;
        if (i0 >= 0 && i0 < LEN) v = *(const u64p*)(xb + i0);  // 8B-aligned (i0 even)
        a[j] = p_mul(v, win8[n]);             // (x_e*w_e, x_o*w_o)
    }
    dft8_p(a, y);
    #pragma unroll
    for (int ka = 1; ka < 8; ka++) {          // scalar cmul (packing costs movs)
        float2 yu = p_up(y[ka]);
        float2 r  = cmul(yu, g_T1[ka * 64 + l]);
        y[ka] = p_pk(r.x, r.y);
    }
    {   // exchange 1 write: idx = 72*n1 + n0 + 8*ka  (conflict-free)
        int n0 = l & 7, n1 = l >> 3;
        #pragma unroll
        for (int ka = 0; ka < 8; ka++) b8[72 * n1 + n0 + 8 * ka] = y[ka];
    }
    FRAME_BAR(f);

    // ---- Pass 2: thread (n0, ka), radix-8 over n1 ----
    {
        int n0 = l & 7, ka = l >> 3;
        #pragma unroll
        for (int n1 = 0; n1 < 8; n1++) a[n1] = b8[72 * n1 + n0 + 8 * ka];
        dft8_p(a, y);
        #pragma unroll
        for (int kc = 1; kc < 8; kc++) {
            float2 yu = p_up(y[kc]);
            float2 r  = cmul(yu, g_T2[kc * 8 + n0]);
            y[kc] = p_pk(r.x, r.y);
        }
        FRAME_BAR(f);      // frame's reads complete before aliased overwrite
        #pragma unroll
        for (int kc = 0; kc < 8; kc++) b8[65 * n0 + kc + 8 * ka] = y[kc];
    }
    FRAME_BAR(f);

    // ---- Pass 3: thread (kc, ka), radix-8 over n0; Z[ka + 8kc + 64kd] ----
    {
        int kc = l & 7, ka = l >> 3;
        #pragma unroll
        for (int n0 = 0; n0 < 8; n0++) a[n0] = b8[65 * n0 + kc + 8 * ka];
        dft8_p(a, y);
        FRAME_BAR(f);      // frame's reads complete before aliased Z write
        float* zre = base;
        float* zim = base + 576;
        #pragma unroll
        for (int kd = 0; kd < 8; kd++) {
            int k  = ka + 8 * kc + 64 * kd;
            int zi = k + 4 * (k >> 5);        // conflict-free scalar layout
            float2 yu = p_up(y[kd]);
            zre[zi] = yu.x;
            zim[zi] = yu.y;
        }
    }
    __syncthreads();       // cross-frame: all Z planes ready, tw ready

    // ---- Fused conjugate-paired untangle + mag/angle + store ----
    // Thread (k0 = tid>>3, ff = tid&7): k = k0+64r (r<4) and pair 512-k from
    // the same Z reads, packed lane math with single rounding per component.
    // Special: at (k0==0, r==0) the pair bin is k=512 where si+ux == 0
    // exactly; Yi must be +0 (not -0) so atan2 gives +pi like numpy.
    {
        float* __restrict__ mag_out = out;
        float* __restrict__ ang_out = out + PLANE;
        const int k0 = tid >> 3;        // 0..63
        const int ff = tid & 7;
        const float* zre = fbuf[ff];
        const float* zim = fbuf[ff] + 576;
        if (t0 + ff < NFRM) {
            unsigned o1 = (unsigned)(b * CUT + k0)        * NFRM + (unsigned)(t0 + ff);
            unsigned o2 = (unsigned)(b * CUT + (512 - k0))* NFRM + (unsigned)(t0 + ff);
            #pragma unroll
            for (int r = 0; r < 4; r++) {
                int k  = k0 + 64 * r;          // [0, 256)
                int i2 = (512 - k) & 511;
                int z1 = k  + 4 * (k  >> 5);
                int z2 = i2 + 4 * (i2 >> 5);
                u64p A  = p_pk(zre[z1], zim[z1]);
                u64p Bc = p_pk(zre[z2], -zim[z2]);         // conj
                u64p S  = p_add(A, Bc);                    // (sr, si)
                u64p Dd = p_sub(A, Bc);                    // (dr, di)
                float2 d2 = p_up(Dd);
                float2 w  = tw[k];
                float uy = fmaf(w.x, d2.y,  w.y * d2.x);   // Im(w*(A-B))
                float ux = fmaf(w.x, d2.x, -w.y * d2.y);   // Re(w*(A-B))
                u64p U2 = p_pk(uy, ux);
                float2 V  = p_up(p_add(S, U2));            // (sr+uy, si+ux)
                float2 Dv = p_up(p_sub(S, U2));            // (sr-uy, si-ux)
                float2 X = p_up(p_mul(p_pk(V.x, Dv.y), (u64p)PHALF));   // (Xr, Xi)
                float2 Y = p_up(p_mul(p_pk(Dv.x, V.y), (u64p)PHALFN));  // (Yr, -0.5(si+ux))
                if (r == 0 && k0 == 0) Y.y = 0.0f;         // k=512: pin Yi = +0
                mag_out[o1] = fast_sqrtf(fmaf(X.x, X.x, X.y * X.y));
                ang_out[o1] = fast_atan2f(X.y, X.x);
                mag_out[o2] = fast_sqrtf(fmaf(Y.x, Y.x, Y.y * Y.y));
                ang_out[o2] = fast_atan2f(Y.y, Y.x);
                o1 += 64u * NFRM;
                o2 -= 64u * NFRM;
            }
            if (k0 == 0) {                     // self-paired bin k = 256
                float Ax = zre[288], Ay = zim[288];    // z(256) = 256 + 4*8
                unsigned o = (unsigned)(b * CUT + 256) * NFRM + (unsigned)(t0 + ff);
                mag_out[o] = fast_sqrtf(fmaf(Ax, Ax, Ay * Ay));
                ang_out[o] = fast_atan2f(-Ay, Ax);     // X[256] = conj(Z[256])
            }
        }
    }
}

extern "C" void kernel_launch(void* const* d_in, const int* in_sizes, int n_in,
                              void* d_out, int out_size) {
    const float* x = (const float*)d_in[0];   // (32, 1, 262144) fp32
    float* out = (float*)d_out;               // mag plane then angle plane
    init_tables<<<(INIT_ENTRIES + 255) / 256, 256>>>();
    dim3 grid((NFRM + TB - 1) / TB, NB);      // 129 x 32
    stft_kernel<<<grid, 512>>>(x, out);
}